// round 3
// baseline (speedup 1.0000x reference)
#include <cuda_runtime.h>
#include <cuda_bf16.h>
#include <cstdint>

// Problem constants
#define BB   8192
#define DIN  2048
#define HH   2048
#define K1   4096   // IN + H
#define K2S  6144   // 3 * IN  (split GEMM2: [Ahi|Ahi|Alo] x [Whi|Wlo|Whi])

// ---------------------------------------------------------------------------
// Scratch (module-load allocated, allowed)
// ---------------------------------------------------------------------------
__device__ __nv_bfloat16 g_concat_bf16[(size_t)BB * K1];   // [B, IN+H] bf16 (hi only)
__device__ __nv_bfloat16 g_gw_bf16[(size_t)HH * K1];       // [H, IN+H] bf16 (hi only)
__device__ __nv_bfloat16 g_in2[(size_t)BB * K2S];          // [B, 3*IN]  = [Ahi|Ahi|Alo]
__device__ __nv_bfloat16 g_wi2[(size_t)HH * K2S];          // [H, 3*IN]  = [Whi|Wlo|Whi]

// Output layout (floats): new_h | concat | pre_gate | gate | values | pre_h
#define OFF_NEWH    ((size_t)0)
#define OFF_CONCAT  ((size_t)BB * HH)
#define OFF_PREGATE (OFF_CONCAT + (size_t)BB * K1)
#define OFF_GATE    (OFF_PREGATE + (size_t)BB * HH)
#define OFF_VALUES  (OFF_GATE + (size_t)BB * HH)
#define OFF_PREH    (OFF_VALUES + (size_t)BB * HH)

// ---------------------------------------------------------------------------
// Helpers
// ---------------------------------------------------------------------------
__device__ __forceinline__ uint2 pack4_bf16(float4 v) {
    __nv_bfloat162 lo = __floats2bfloat162_rn(v.x, v.y);
    __nv_bfloat162 hi = __floats2bfloat162_rn(v.z, v.w);
    uint2 u;
    u.x = *reinterpret_cast<unsigned*>(&lo);
    u.y = *reinterpret_cast<unsigned*>(&hi);
    return u;
}

// hi = bf16(v) (as float4), returned for residual computation
__device__ __forceinline__ float4 bf16_round4(float4 v) {
    float4 h;
    h.x = __bfloat162float(__float2bfloat16_rn(v.x));
    h.y = __bfloat162float(__float2bfloat16_rn(v.y));
    h.z = __bfloat162float(__float2bfloat16_rn(v.z));
    h.w = __bfloat162float(__float2bfloat16_rn(v.w));
    return h;
}

__device__ __forceinline__ void cp_async16(uint32_t saddr, const void* gptr) {
    asm volatile("cp.async.ca.shared.global [%0], [%1], 16;" :: "r"(saddr), "l"(gptr));
}

// ---------------------------------------------------------------------------
// Kernel 1: convert inputs to bf16 (+ residual split for GEMM2 operands),
//           and emit concat_input output region.
// ---------------------------------------------------------------------------
#define N0 ((size_t)BB * DIN / 4)   // input  float4s
#define N1 ((size_t)BB * HH  / 4)   // state  float4s
#define N2 ((size_t)HH * K1  / 4)   // gate_w float4s
#define N3 ((size_t)HH * DIN / 4)   // w_i    float4s
#define NTOT (N0 + N1 + N2 + N3)

__global__ void __launch_bounds__(256) convert_kernel(
    const float4* __restrict__ inp,
    const float4* __restrict__ st,
    const float4* __restrict__ gw,
    const float4* __restrict__ wi,
    float4* __restrict__ out_concat)   // d_out + OFF_CONCAT
{
    size_t idx = (size_t)blockIdx.x * blockDim.x + threadIdx.x;
    if (idx >= NTOT) return;

    uint2* cbf  = reinterpret_cast<uint2*>(g_concat_bf16);
    uint2* gwbf = reinterpret_cast<uint2*>(g_gw_bf16);
    uint2* in2  = reinterpret_cast<uint2*>(g_in2);
    uint2* wi2  = reinterpret_cast<uint2*>(g_wi2);

    if (idx < N0) {
        // input: [B, 2048] -> concat copy, concat bf16, and split for GEMM2
        float4 v = inp[idx];
        size_t row = idx >> 9;          // 512 float4 per row
        size_t c   = idx & 511;
        out_concat[row * 1024 + c] = v;               // concat stride 1024 f4
        float4 h = bf16_round4(v);
        uint2 hp = pack4_bf16(h);
        cbf[row * 1024 + c] = hp;                     // GEMM1 A (hi)
        // GEMM2 A = [Ahi | Ahi | Alo], row stride 1536 chunks
        in2[row * 1536 + c]        = hp;
        in2[row * 1536 + 512 + c]  = hp;
        float4 l = make_float4(v.x - h.x, v.y - h.y, v.z - h.z, v.w - h.w);
        in2[row * 1536 + 1024 + c] = pack4_bf16(l);
    } else if (idx < N0 + N1) {
        size_t i = idx - N0;
        float4 v = st[i];
        size_t row = i >> 9;
        size_t c   = i & 511;
        out_concat[row * 1024 + 512 + c] = v;
        cbf[row * 1024 + 512 + c] = pack4_bf16(v);
    } else if (idx < N0 + N1 + N2) {
        size_t i = idx - N0 - N1;
        gwbf[i] = pack4_bf16(gw[i]);
    } else {
        // weights_i: [H, 2048] -> split for GEMM2: [Whi | Wlo | Whi]
        size_t i = idx - N0 - N1 - N2;
        float4 v = wi[i];
        size_t row = i >> 9;
        size_t c   = i & 511;
        float4 h = bf16_round4(v);
        uint2 hp = pack4_bf16(h);
        wi2[row * 1536 + c]        = hp;
        float4 l = make_float4(v.x - h.x, v.y - h.y, v.z - h.z, v.w - h.w);
        wi2[row * 1536 + 512 + c]  = pack4_bf16(l);
        wi2[row * 1536 + 1024 + c] = hp;
    }
}

// ---------------------------------------------------------------------------
// GEMM: C[B,H] = A_bf16[B,K] @ W_bf16[H,K]^T  with fused epilogues
//   EPI==1 : A=g_concat_bf16, W=g_gw_bf16;  pre_gate = acc + bias ; gate = clip
//   EPI==2 : A=g_in2,         W=g_wi2;      values = tanh(acc); pre_h; new_h
// NOTE: operand pointers are taken from __device__ symbols INSIDE the kernel
// (host code cannot take the address of a __device__ variable).
// Tile: 128x128x32, 256 threads (warp grid 4x2, warp tile 32x64), 2-stage cp.async
// ---------------------------------------------------------------------------
template<int KDIM, int EPI>
__global__ void __launch_bounds__(256) gemm_kernel(
    const float* __restrict__ bias,
    const float* __restrict__ state,
    const float* __restrict__ gate_in,
    float* __restrict__ out0,
    float* __restrict__ out1,
    float* __restrict__ out2)
{
    __shared__ __align__(16) __nv_bfloat16 sA[2][128][40];
    __shared__ __align__(16) __nv_bfloat16 sB[2][128][40];

    const __nv_bfloat16* __restrict__ A  = (EPI == 1) ? g_concat_bf16 : g_in2;
    const __nv_bfloat16* __restrict__ Bw = (EPI == 1) ? g_gw_bf16     : g_wi2;

    const int tid  = threadIdx.x;
    const int bm   = blockIdx.y;
    const int bn   = blockIdx.x;
    const int warp = tid >> 5;
    const int lane = tid & 31;
    const int wm   = warp & 3;   // 0..3 -> rows wm*32
    const int wn   = warp >> 2;  // 0..1 -> cols wn*64

    const int KT = KDIM / 32;

    float acc[2][8][4];
    #pragma unroll
    for (int i = 0; i < 2; i++)
        #pragma unroll
        for (int j = 0; j < 8; j++)
            #pragma unroll
            for (int k = 0; k < 4; k++) acc[i][j][k] = 0.f;

    auto load_tile = [&](int buf, int kt) {
        const int k0 = kt * 32;
        #pragma unroll
        for (int i = 0; i < 2; i++) {
            int chunk = tid + i * 256;            // 512 chunks of 16B per operand
            int row = chunk >> 2;
            int col = (chunk & 3) * 8;
            const __nv_bfloat16* gA = A + (size_t)(bm * 128 + row) * KDIM + k0 + col;
            cp_async16((uint32_t)__cvta_generic_to_shared(&sA[buf][row][col]), gA);
            const __nv_bfloat16* gB = Bw + (size_t)(bn * 128 + row) * KDIM + k0 + col;
            cp_async16((uint32_t)__cvta_generic_to_shared(&sB[buf][row][col]), gB);
        }
        asm volatile("cp.async.commit_group;");
    };

    load_tile(0, 0);

    #pragma unroll 1
    for (int kt = 0; kt < KT; kt++) {
        const int cur = kt & 1;
        if (kt + 1 < KT) {
            load_tile(cur ^ 1, kt + 1);
            asm volatile("cp.async.wait_group 1;");
        } else {
            asm volatile("cp.async.wait_group 0;");
        }
        __syncthreads();

        #pragma unroll
        for (int kk = 0; kk < 2; kk++) {
            uint32_t aa[2][4], bb[4][4];
            const int lr = lane & 15;
            const int lc = ((lane >> 4) * 8) + kk * 16;
            #pragma unroll
            for (int mt = 0; mt < 2; mt++) {
                uint32_t ad = (uint32_t)__cvta_generic_to_shared(&sA[cur][wm * 32 + mt * 16 + lr][lc]);
                asm volatile("ldmatrix.sync.aligned.m8n8.x4.shared.b16 {%0,%1,%2,%3}, [%4];"
                             : "=r"(aa[mt][0]), "=r"(aa[mt][1]), "=r"(aa[mt][2]), "=r"(aa[mt][3])
                             : "r"(ad));
            }
            #pragma unroll
            for (int l = 0; l < 4; l++) {
                uint32_t ad = (uint32_t)__cvta_generic_to_shared(&sB[cur][wn * 64 + l * 16 + lr][lc]);
                asm volatile("ldmatrix.sync.aligned.m8n8.x4.shared.b16 {%0,%1,%2,%3}, [%4];"
                             : "=r"(bb[l][0]), "=r"(bb[l][1]), "=r"(bb[l][2]), "=r"(bb[l][3])
                             : "r"(ad));
            }
            #pragma unroll
            for (int mt = 0; mt < 2; mt++) {
                #pragma unroll
                for (int n = 0; n < 8; n++) {
                    uint32_t b0 = bb[n >> 1][n & 1];
                    uint32_t b1 = bb[n >> 1][(n & 1) + 2];
                    asm volatile(
                        "mma.sync.aligned.m16n8k16.row.col.f32.bf16.bf16.f32 "
                        "{%0,%1,%2,%3}, {%4,%5,%6,%7}, {%8,%9}, {%0,%1,%2,%3};"
                        : "+f"(acc[mt][n][0]), "+f"(acc[mt][n][1]),
                          "+f"(acc[mt][n][2]), "+f"(acc[mt][n][3])
                        : "r"(aa[mt][0]), "r"(aa[mt][1]), "r"(aa[mt][2]), "r"(aa[mt][3]),
                          "r"(b0), "r"(b1));
                }
            }
        }
        __syncthreads();
    }

    // ---- epilogue ----
    const int rbase = bm * 128 + wm * 32 + (lane >> 2);
    const int cbase = bn * 128 + wn * 64 + (lane & 3) * 2;

    #pragma unroll
    for (int mt = 0; mt < 2; mt++) {
        #pragma unroll
        for (int n = 0; n < 8; n++) {
            const int col = cbase + n * 8;
            #pragma unroll
            for (int h = 0; h < 2; h++) {
                const int r = rbase + mt * 16 + h * 8;
                const size_t off = (size_t)r * HH + col;
                const float x0 = acc[mt][n][h * 2 + 0];
                const float x1 = acc[mt][n][h * 2 + 1];
                if (EPI == 1) {
                    const float2 b2 = *reinterpret_cast<const float2*>(bias + col);
                    float p0 = x0 + b2.x, p1 = x1 + b2.y;
                    *reinterpret_cast<float2*>(out0 + off) = make_float2(p0, p1);  // pre_gate
                    float2 gt = make_float2(fminf(fmaxf(p0, 0.f), 1.f),
                                            fminf(fmaxf(p1, 0.f), 1.f));
                    *reinterpret_cast<float2*>(out1 + off) = gt;                   // gate
                } else {
                    const float2 g = *reinterpret_cast<const float2*>(gate_in + off);
                    const float2 s = *reinterpret_cast<const float2*>(state + off);
                    const float v0 = tanhf(x0);
                    const float v1 = tanhf(x1);
                    const float ph0 = s.x * (1.f - g.x) + v0 * g.x;
                    const float ph1 = s.y * (1.f - g.y) + v1 * g.y;
                    *reinterpret_cast<float2*>(out0 + off) = make_float2(v0, v1);          // values
                    *reinterpret_cast<float2*>(out1 + off) = make_float2(ph0, ph1);        // pre_h
                    *reinterpret_cast<float2*>(out2 + off) = make_float2(fmaxf(ph0, 0.f),
                                                                         fmaxf(ph1, 0.f)); // new_h
                }
            }
        }
    }
}

// ---------------------------------------------------------------------------
// Launch
// ---------------------------------------------------------------------------
extern "C" void kernel_launch(void* const* d_in, const int* in_sizes, int n_in,
                              void* d_out, int out_size)
{
    const float* input = (const float*)d_in[0];   // [B, IN]
    const float* state = (const float*)d_in[1];   // [B, H]
    const float* gw    = (const float*)d_in[2];   // [H, IN+H]
    const float* bias  = (const float*)d_in[3];   // [H]
    const float* wi    = (const float*)d_in[4];   // [H, IN]
    float* out = (float*)d_out;

    // 1) convert + concat copy + precision split
    {
        const size_t total = NTOT;
        const int threads = 256;
        const int blocks = (int)((total + threads - 1) / threads);
        convert_kernel<<<blocks, threads>>>(
            (const float4*)input, (const float4*)state,
            (const float4*)gw, (const float4*)wi,
            (float4*)(out + OFF_CONCAT));
    }

    // 2) GEMM1: pre_gate / gate   (plain bf16, error anchored by bias)
    {
        dim3 grid(HH / 128, BB / 128);   // (16, 64)
        gemm_kernel<K1, 1><<<grid, 256>>>(
            bias, nullptr, nullptr,
            out + OFF_PREGATE, out + OFF_GATE, nullptr);
    }

    // 3) GEMM2: values / pre_h / new_h  (split bf16, K=3*IN)
    {
        dim3 grid(HH / 128, BB / 128);
        gemm_kernel<K2S, 2><<<grid, 256>>>(
            nullptr, state, out + OFF_GATE,
            out + OFF_VALUES, out + OFF_PREH, out + OFF_NEWH);
    }
}

// round 6
// speedup vs baseline: 1.5429x; 1.5429x over previous
#include <cuda_runtime.h>
#include <cuda_fp16.h>
#include <cstdint>

// Problem constants
#define BB   8192
#define DIN  2048
#define HH   2048
#define K1   4096   // IN + H
#define K2   2048   // IN

// ---------------------------------------------------------------------------
// Scratch (module-load allocated, allowed)
// ---------------------------------------------------------------------------
__device__ __align__(128) __half g_concat_f16[(size_t)BB * K1];  // [B, IN+H] fp16
__device__ __align__(128) __half g_gw_f16[(size_t)HH * K1];      // [H, IN+H] fp16
__device__ __align__(128) __half g_wi_f16[(size_t)HH * K2];      // [H, IN]   fp16

// Output layout (floats): new_h | concat | pre_gate | gate | values | pre_h
#define OFF_NEWH    ((size_t)0)
#define OFF_CONCAT  ((size_t)BB * HH)
#define OFF_PREGATE (OFF_CONCAT + (size_t)BB * K1)
#define OFF_GATE    (OFF_PREGATE + (size_t)BB * HH)
#define OFF_VALUES  (OFF_GATE + (size_t)BB * HH)
#define OFF_PREH    (OFF_VALUES + (size_t)BB * HH)

// ---------------------------------------------------------------------------
// Helpers
// ---------------------------------------------------------------------------
__device__ __forceinline__ uint2 pack4_f16(float4 v) {
    __half2 lo = __floats2half2_rn(v.x, v.y);
    __half2 hi = __floats2half2_rn(v.z, v.w);
    uint2 u;
    u.x = *reinterpret_cast<unsigned*>(&lo);
    u.y = *reinterpret_cast<unsigned*>(&hi);
    return u;
}

__device__ __forceinline__ void cp_async16(uint32_t saddr, const void* gptr) {
    asm volatile("cp.async.ca.shared.global [%0], [%1], 16;" :: "r"(saddr), "l"(gptr));
}

// ---------------------------------------------------------------------------
// Kernel 1: convert inputs to fp16 + emit concat_input output region
// ---------------------------------------------------------------------------
#define N0 ((size_t)BB * DIN / 4)   // input  float4s
#define N1 ((size_t)BB * HH  / 4)   // state  float4s
#define N2 ((size_t)HH * K1  / 4)   // gate_w float4s
#define N3 ((size_t)HH * K2  / 4)   // w_i    float4s
#define NTOT (N0 + N1 + N2 + N3)

__global__ void __launch_bounds__(256) convert_kernel(
    const float4* __restrict__ inp,
    const float4* __restrict__ st,
    const float4* __restrict__ gw,
    const float4* __restrict__ wi,
    float4* __restrict__ out_concat)   // d_out + OFF_CONCAT
{
    size_t idx = (size_t)blockIdx.x * blockDim.x + threadIdx.x;
    if (idx >= NTOT) return;

    uint2* cf  = reinterpret_cast<uint2*>(g_concat_f16);
    uint2* gwf = reinterpret_cast<uint2*>(g_gw_f16);
    uint2* wif = reinterpret_cast<uint2*>(g_wi_f16);

    if (idx < N0) {
        float4 v = inp[idx];
        size_t row = idx >> 9;          // 512 float4 per row
        size_t c   = idx & 511;
        out_concat[row * 1024 + c] = v;           // concat stride = 1024 f4
        cf[row * 1024 + c] = pack4_f16(v);
    } else if (idx < N0 + N1) {
        size_t i = idx - N0;
        float4 v = st[i];
        size_t row = i >> 9;
        size_t c   = i & 511;
        out_concat[row * 1024 + 512 + c] = v;
        cf[row * 1024 + 512 + c] = pack4_f16(v);
    } else if (idx < N0 + N1 + N2) {
        size_t i = idx - N0 - N1;
        gwf[i] = pack4_f16(gw[i]);
    } else {
        size_t i = idx - N0 - N1 - N2;
        wif[i] = pack4_f16(wi[i]);
    }
}

// ---------------------------------------------------------------------------
// GEMM: C[B,H] = A_f16[B,K] @ W_f16[H,K]^T  with fused epilogues
//   EPI==1 : A = g_concat_f16 (lda=K1, K=K1), W = g_gw_f16
//            pre_gate = acc + bias ; gate = clip(pre_gate, 0, 1)
//   EPI==2 : A = g_concat_f16 cols [0,2048) (lda=K1, K=K2), W = g_wi_f16
//            values = tanh(acc); pre_h = state*(1-g)+values*g; new_h = relu
// Tile: 128x128x32, 256 threads (warp grid 4x2, warp tile 32x64), 2-stage cp.async
// ---------------------------------------------------------------------------
template<int KDIM, int EPI>
__global__ void __launch_bounds__(256) gemm_kernel(
    const float* __restrict__ bias,
    const float* __restrict__ state,
    const float* __restrict__ gate_in,
    float* __restrict__ out0,
    float* __restrict__ out1,
    float* __restrict__ out2)
{
    __shared__ __align__(16) __half sA[2][128][40];
    __shared__ __align__(16) __half sB[2][128][40];

    const __half* __restrict__ A  = g_concat_f16;                    // lda = K1 always
    const __half* __restrict__ Bw = (EPI == 1) ? g_gw_f16 : g_wi_f16; // ldb = KDIM

    const int tid  = threadIdx.x;
    const int bm   = blockIdx.y;
    const int bn   = blockIdx.x;
    const int warp = tid >> 5;
    const int lane = tid & 31;
    const int wm   = warp & 3;   // 0..3 -> rows wm*32
    const int wn   = warp >> 2;  // 0..1 -> cols wn*64

    const int KT = KDIM / 32;

    float acc[2][8][4];
    #pragma unroll
    for (int i = 0; i < 2; i++)
        #pragma unroll
        for (int j = 0; j < 8; j++)
            #pragma unroll
            for (int k = 0; k < 4; k++) acc[i][j][k] = 0.f;

    auto load_tile = [&](int buf, int kt) {
        const int k0 = kt * 32;
        #pragma unroll
        for (int i = 0; i < 2; i++) {
            int chunk = tid + i * 256;            // 512 chunks of 16B per operand
            int row = chunk >> 2;
            int col = (chunk & 3) * 8;
            const __half* gA = A + (size_t)(bm * 128 + row) * K1 + k0 + col;
            cp_async16((uint32_t)__cvta_generic_to_shared(&sA[buf][row][col]), gA);
            const __half* gB = Bw + (size_t)(bn * 128 + row) * KDIM + k0 + col;
            cp_async16((uint32_t)__cvta_generic_to_shared(&sB[buf][row][col]), gB);
        }
        asm volatile("cp.async.commit_group;");
    };

    load_tile(0, 0);

    #pragma unroll 1
    for (int kt = 0; kt < KT; kt++) {
        const int cur = kt & 1;
        if (kt + 1 < KT) {
            load_tile(cur ^ 1, kt + 1);
            asm volatile("cp.async.wait_group 1;");
        } else {
            asm volatile("cp.async.wait_group 0;");
        }
        __syncthreads();

        #pragma unroll
        for (int kk = 0; kk < 2; kk++) {
            uint32_t aa[2][4], bb[4][4];
            const int lr = lane & 15;
            const int lc = ((lane >> 4) * 8) + kk * 16;
            #pragma unroll
            for (int mt = 0; mt < 2; mt++) {
                uint32_t ad = (uint32_t)__cvta_generic_to_shared(&sA[cur][wm * 32 + mt * 16 + lr][lc]);
                asm volatile("ldmatrix.sync.aligned.m8n8.x4.shared.b16 {%0,%1,%2,%3}, [%4];"
                             : "=r"(aa[mt][0]), "=r"(aa[mt][1]), "=r"(aa[mt][2]), "=r"(aa[mt][3])
                             : "r"(ad));
            }
            #pragma unroll
            for (int l = 0; l < 4; l++) {
                uint32_t ad = (uint32_t)__cvta_generic_to_shared(&sB[cur][wn * 64 + l * 16 + lr][lc]);
                asm volatile("ldmatrix.sync.aligned.m8n8.x4.shared.b16 {%0,%1,%2,%3}, [%4];"
                             : "=r"(bb[l][0]), "=r"(bb[l][1]), "=r"(bb[l][2]), "=r"(bb[l][3])
                             : "r"(ad));
            }
            #pragma unroll
            for (int mt = 0; mt < 2; mt++) {
                #pragma unroll
                for (int n = 0; n < 8; n++) {
                    uint32_t b0 = bb[n >> 1][n & 1];
                    uint32_t b1 = bb[n >> 1][(n & 1) + 2];
                    asm volatile(
                        "mma.sync.aligned.m16n8k16.row.col.f32.f16.f16.f32 "
                        "{%0,%1,%2,%3}, {%4,%5,%6,%7}, {%8,%9}, {%0,%1,%2,%3};"
                        : "+f"(acc[mt][n][0]), "+f"(acc[mt][n][1]),
                          "+f"(acc[mt][n][2]), "+f"(acc[mt][n][3])
                        : "r"(aa[mt][0]), "r"(aa[mt][1]), "r"(aa[mt][2]), "r"(aa[mt][3]),
                          "r"(b0), "r"(b1));
                }
            }
        }
        __syncthreads();
    }

    // ---- epilogue ----
    const int rbase = bm * 128 + wm * 32 + (lane >> 2);
    const int cbase = bn * 128 + wn * 64 + (lane & 3) * 2;

    #pragma unroll
    for (int mt = 0; mt < 2; mt++) {
        #pragma unroll
        for (int n = 0; n < 8; n++) {
            const int col = cbase + n * 8;
            #pragma unroll
            for (int h = 0; h < 2; h++) {
                const int r = rbase + mt * 16 + h * 8;
                const size_t off = (size_t)r * HH + col;
                const float x0 = acc[mt][n][h * 2 + 0];
                const float x1 = acc[mt][n][h * 2 + 1];
                if (EPI == 1) {
                    const float2 b2 = *reinterpret_cast<const float2*>(bias + col);
                    float p0 = x0 + b2.x, p1 = x1 + b2.y;
                    *reinterpret_cast<float2*>(out0 + off) = make_float2(p0, p1);  // pre_gate
                    float2 gt = make_float2(fminf(fmaxf(p0, 0.f), 1.f),
                                            fminf(fmaxf(p1, 0.f), 1.f));
                    *reinterpret_cast<float2*>(out1 + off) = gt;                   // gate
                } else {
                    const float2 g = *reinterpret_cast<const float2*>(gate_in + off);
                    const float2 s = *reinterpret_cast<const float2*>(state + off);
                    const float v0 = tanhf(x0);
                    const float v1 = tanhf(x1);
                    const float ph0 = s.x * (1.f - g.x) + v0 * g.x;
                    const float ph1 = s.y * (1.f - g.y) + v1 * g.y;
                    *reinterpret_cast<float2*>(out0 + off) = make_float2(v0, v1);          // values
                    *reinterpret_cast<float2*>(out1 + off) = make_float2(ph0, ph1);        // pre_h
                    *reinterpret_cast<float2*>(out2 + off) = make_float2(fmaxf(ph0, 0.f),
                                                                         fmaxf(ph1, 0.f)); // new_h
                }
            }
        }
    }
}

// ---------------------------------------------------------------------------
// Launch
// ---------------------------------------------------------------------------
extern "C" void kernel_launch(void* const* d_in, const int* in_sizes, int n_in,
                              void* d_out, int out_size)
{
    const float* input = (const float*)d_in[0];   // [B, IN]
    const float* state = (const float*)d_in[1];   // [B, H]
    const float* gw    = (const float*)d_in[2];   // [H, IN+H]
    const float* bias  = (const float*)d_in[3];   // [H]
    const float* wi    = (const float*)d_in[4];   // [H, IN]
    float* out = (float*)d_out;

    // 1) convert + concat copy
    {
        const int threads = 256;
        const int blocks = (int)((NTOT + threads - 1) / threads);
        convert_kernel<<<blocks, threads>>>(
            (const float4*)input, (const float4*)state,
            (const float4*)gw, (const float4*)wi,
            (float4*)(out + OFF_CONCAT));
    }

    // 2) GEMM1: pre_gate / gate  (K=4096)
    {
        dim3 grid(HH / 128, BB / 128);   // (16, 64)
        gemm_kernel<K1, 1><<<grid, 256>>>(
            bias, nullptr, nullptr,
            out + OFF_PREGATE, out + OFF_GATE, nullptr);
    }

    // 3) GEMM2: values / pre_h / new_h  (K=2048, A = concat cols [0,2048))
    {
        dim3 grid(HH / 128, BB / 128);
        gemm_kernel<K2, 2><<<grid, 256>>>(
            nullptr, state, out + OFF_GATE,
            out + OFF_VALUES, out + OFF_PREH, out + OFF_NEWH);
    }
}